// round 1
// baseline (speedup 1.0000x reference)
#include <cuda_runtime.h>
#include <math.h>

// ---------------- problem constants ----------------
#define BB 2
#define SS 64
#define LL 256
#define CC 192
#define C4 768
#define HH 4
#define DH 48
#define TT (BB*SS*LL)      // 32768 tokens
#define NBLK 6

// ---------------- scratch (device globals; no runtime alloc) ----------------
__device__ float g_x[TT*CC];   // residual stream, layout (b,s,l,c) token-major
__device__ float g_h[TT*CC];   // LN output / attention output (reused)
__device__ float g_q[TT*CC];
__device__ float g_k[TT*CC];
__device__ float g_v[TT*CC];
__device__ float g_f1[TT*C4];  // FFN hidden

// ---------------- activation helpers ----------------
__device__ __forceinline__ float elu1(float v) {           // elu(v)+1
    return v > 0.0f ? v + 1.0f : expf(v);
}
__device__ __forceinline__ float gelu_exact(float v) {
    return 0.5f * v * (1.0f + erff(v * 0.70710678118654752f));
}

// ============================================================
// Kernel 1: embedding lookup + projection (64->192) + rotary over L
// one block per token, 192 threads
// ============================================================
__global__ void embed_kernel(const int* __restrict__ tokens,
                             const float* __restrict__ emb,
                             const float* __restrict__ pw,   // (192,64)
                             const float* __restrict__ pb,   // (192,)
                             float* __restrict__ out) {
    int t = blockIdx.x;
    int c = threadIdx.x;
    __shared__ float e[64];
    __shared__ float xv[CC];
    __shared__ float invf[96];
    if (c < 64) e[c] = emb[tokens[t] * 64 + c];
    if (c >= 64 && c < 160) {
        int j = c - 64;
        invf[j] = powf(10000.0f, -(float)j / 96.0f);
    }
    __syncthreads();
    float s = pb[c];
    const float* wr = pw + c * 64;
    #pragma unroll
    for (int i = 0; i < 64; i++) s += e[i] * wr[i];
    xv[c] = s;
    __syncthreads();
    int l = t & (LL - 1);                 // position along L
    int c2 = (c < 96) ? c : c - 96;
    float a = (float)l * invf[c2];
    float cs = cosf(a), sn = sinf(a);
    float rot = (c < 96) ? -xv[c + 96] : xv[c - 96];
    out[(size_t)t * CC + c] = s * cs + rot * sn;
}

// ============================================================
// Kernel 2: LayerNorm over the 192 channels of each token
// blockDim (32,8): one warp per token
// ============================================================
__global__ void ln_kernel(const float* __restrict__ x, float* __restrict__ h,
                          const float* __restrict__ g, const float* __restrict__ b) {
    int t = blockIdx.x * 8 + threadIdx.y;
    int lane = threadIdx.x;
    const float* xr = x + (size_t)t * CC;
    float v[6];
    float s = 0.f, ss = 0.f;
    #pragma unroll
    for (int i = 0; i < 6; i++) {
        v[i] = xr[lane + i * 32];
        s += v[i]; ss += v[i] * v[i];
    }
    #pragma unroll
    for (int o = 16; o; o >>= 1) {
        s  += __shfl_xor_sync(0xffffffffu, s, o);
        ss += __shfl_xor_sync(0xffffffffu, ss, o);
    }
    float m   = s * (1.0f / CC);
    float var = ss * (1.0f / CC) - m * m;
    float r   = rsqrtf(var + 1e-5f);
    float* hr = h + (size_t)t * CC;
    #pragma unroll
    for (int i = 0; i < 6; i++) {
        int c = lane + i * 32;
        hr[c] = (v[i] - m) * r * g[c] + b[c];
    }
}

// ============================================================
// Kernel 3: generic fp32 GEMM  C[t,o] = act( A[t,:K] . W[o,:K] + bias[o] ) (+ C)
// A: (T,K) row-major, W: (N,K) row-major. Tiles 128x64x16, 256 thr, 8x4 micro.
// act: 0 none, 1 (elu+1)/sqrt(48), 2 elu+1, 3 gelu ; accFlag: += existing
// All dims are exact multiples of the tile (T=32768, N in {192,768}, K in {192,768}).
// ============================================================
#define BM 128
#define BN 64
#define BK 16
__global__ __launch_bounds__(256) void gemm_kernel(
        const float* __restrict__ A, const float* __restrict__ W,
        const float* __restrict__ bias, float* __restrict__ Cout,
        int K, int N, int act, int accFlag) {
    __shared__ float As[BK][BM + 4];
    __shared__ float Bs[BK][BN + 4];
    int tid = threadIdx.x;
    int row0 = blockIdx.x * BM;
    int col0 = blockIdx.y * BN;
    int tx = tid & 15;        // 0..15 -> 4 cols
    int ty = tid >> 4;        // 0..15 -> 8 rows
    float acc[8][4];
    #pragma unroll
    for (int i = 0; i < 8; i++)
        #pragma unroll
        for (int j = 0; j < 4; j++) acc[i][j] = 0.f;

    for (int k0 = 0; k0 < K; k0 += BK) {
        #pragma unroll
        for (int i = 0; i < 8; i++) {                 // A tile: 2048 elems
            int lin = tid + i * 256;
            int kk = lin & (BK - 1);
            int mm = lin >> 4;
            As[kk][mm] = A[(size_t)(row0 + mm) * K + k0 + kk];
        }
        #pragma unroll
        for (int i = 0; i < 4; i++) {                 // B tile: 1024 elems
            int lin = tid + i * 256;
            int kk = lin & (BK - 1);
            int nn = lin >> 4;
            Bs[kk][nn] = W[(size_t)(col0 + nn) * K + k0 + kk];
        }
        __syncthreads();
        #pragma unroll
        for (int kk = 0; kk < BK; kk++) {
            float4 a0 = *(const float4*)&As[kk][ty * 8];
            float4 a1 = *(const float4*)&As[kk][ty * 8 + 4];
            float4 b0 = *(const float4*)&Bs[kk][tx * 4];
            float a[8] = {a0.x, a0.y, a0.z, a0.w, a1.x, a1.y, a1.z, a1.w};
            float b[4] = {b0.x, b0.y, b0.z, b0.w};
            #pragma unroll
            for (int i = 0; i < 8; i++)
                #pragma unroll
                for (int j = 0; j < 4; j++)
                    acc[i][j] += a[i] * b[j];
        }
        __syncthreads();
    }

    #pragma unroll
    for (int i = 0; i < 8; i++) {
        int r = row0 + ty * 8 + i;
        #pragma unroll
        for (int j = 0; j < 4; j++) {
            int c = col0 + tx * 4 + j;
            float v = acc[i][j] + bias[c];
            if (act == 1)      v = elu1(v) * 0.14433756729740643f;  // 1/sqrt(48)
            else if (act == 2) v = elu1(v);
            else if (act == 3) v = gelu_exact(v);
            size_t idx = (size_t)r * N + c;
            if (accFlag) v += Cout[idx];
            Cout[idx] = v;
        }
    }
}

// ============================================================
// Kernel 4: linear attention core per (group, head)
// q already has (elu+1)/sqrt(dh), k has elu+1 applied (GEMM epilogue).
// kv[d,e] = sum_n k[n,d] v[n,e]; ksum[d] = sum_n k[n,d];
// o[n,e] = (sum_d q[n,d] kv[d,e]) / (q[n,:].ksum + 1e-6)
// row (isCol=0): group=(b,s), N=256, tokens contiguous
// col (isCol=1): group=(b,l), N=64, tokens strided by L
// ============================================================
__global__ __launch_bounds__(256) void attn_kernel(
        const float* __restrict__ q, const float* __restrict__ k,
        const float* __restrict__ v, float* __restrict__ o,
        int N, int isCol) {
    extern __shared__ float sm[];
    float* ks   = sm;                 // N*48
    float* vs   = sm + N * DH;        // N*48
    float* kv   = vs + N * DH;        // 48*48
    float* ksum = kv + DH * DH;       // 48
    int g = blockIdx.x, h = blockIdx.y;
    int tid = threadIdx.x;

    // token index for slot n within this group
    // row: t = g*256 + n ; col: t = ((g>>8)*64 + n)*256 + (g&255)
    // phase 1: load k,v tiles (vectorized float4)
    for (int lin = tid; lin < N * (DH / 4); lin += 256) {
        int n = lin / (DH / 4);
        int j = lin - n * (DH / 4);
        int t = isCol ? ((((g >> 8) * SS + n) << 8) + (g & 255)) : g * N + n;
        size_t base = (size_t)t * CC + h * DH;
        ((float4*)ks)[n * (DH / 4) + j] = *(const float4*)(k + base + j * 4);
        ((float4*)vs)[n * (DH / 4) + j] = *(const float4*)(v + base + j * 4);
    }
    __syncthreads();

    if (tid < DH) {
        float s = 0.f;
        for (int n = 0; n < N; n++) s += ks[n * DH + tid];
        ksum[tid] = s;
    }
    for (int p = tid; p < DH * DH; p += 256) {
        int d = p / DH, e = p - d * DH;
        float s = 0.f;
        for (int n = 0; n < N; n++) s += ks[n * DH + d] * vs[n * DH + e];
        kv[p] = s;
    }
    __syncthreads();

    for (int n = tid; n < N; n += 256) {
        int t = isCol ? ((((g >> 8) * SS + n) << 8) + (g & 255)) : g * N + n;
        size_t base = (size_t)t * CC + h * DH;
        float qr[DH];
        #pragma unroll
        for (int j = 0; j < DH / 4; j++) {
            float4 f = *(const float4*)(q + base + j * 4);
            qr[4*j] = f.x; qr[4*j+1] = f.y; qr[4*j+2] = f.z; qr[4*j+3] = f.w;
        }
        float qk = 0.f;
        #pragma unroll
        for (int d = 0; d < DH; d++) qk += qr[d] * ksum[d];
        float z = 1.0f / (qk + 1e-6f);
        float ov[DH];
        #pragma unroll
        for (int e = 0; e < DH; e++) ov[e] = 0.f;
        #pragma unroll
        for (int d = 0; d < DH; d++) {
            float qd = qr[d];
            const float4* kvr = (const float4*)&kv[d * DH];
            #pragma unroll
            for (int j = 0; j < DH / 4; j++) {
                float4 kk4 = kvr[j];
                ov[4*j]   += qd * kk4.x;
                ov[4*j+1] += qd * kk4.y;
                ov[4*j+2] += qd * kk4.z;
                ov[4*j+3] += qd * kk4.w;
            }
        }
        #pragma unroll
        for (int j = 0; j < DH / 4; j++) {
            float4 w4 = make_float4(ov[4*j]*z, ov[4*j+1]*z, ov[4*j+2]*z, ov[4*j+3]*z);
            *(float4*)(o + base + j * 4) = w4;
        }
    }
}

// ============================================================
// Kernel 5: head — o = sigmoid(softplus(x . pw + pb)), one warp per token
// ============================================================
__global__ void final_kernel(const float* __restrict__ x,
                             const float* __restrict__ pw,
                             const float* __restrict__ pb,
                             float* __restrict__ out) {
    int t = blockIdx.x * 8 + threadIdx.y;
    int lane = threadIdx.x;
    const float* xr = x + (size_t)t * CC;
    float s = 0.f;
    #pragma unroll
    for (int i = 0; i < 6; i++) {
        int c = lane + i * 32;
        s += xr[c] * pw[c];
    }
    #pragma unroll
    for (int o = 16; o; o >>= 1) s += __shfl_xor_sync(0xffffffffu, s, o);
    if (lane == 0) {
        float ov = s + pb[0];
        float sp = (ov > 20.f) ? ov : log1pf(expf(ov));
        out[t] = 1.0f / (1.0f + expf(-sp));
    }
}

// ============================================================
// Host orchestration
// ============================================================
extern "C" void kernel_launch(void* const* d_in, const int* in_sizes, int n_in,
                              void* d_out, int out_size) {
    const int*   tokens = (const int*)  d_in[0];
    const float* emb    = (const float*)d_in[1];
    const float* proj_w = (const float*)d_in[2];
    const float* proj_b = (const float*)d_in[3];
    const float* ln_g   = (const float*)d_in[4];
    const float* ln_b   = (const float*)d_in[5];
    const float* wq     = (const float*)d_in[6];
    const float* wk     = (const float*)d_in[7];
    const float* wv     = (const float*)d_in[8];
    const float* wo     = (const float*)d_in[9];
    const float* bq     = (const float*)d_in[10];
    const float* bk     = (const float*)d_in[11];
    const float* bv     = (const float*)d_in[12];
    const float* bo     = (const float*)d_in[13];
    const float* ffn_w1 = (const float*)d_in[14];
    const float* ffn_b1 = (const float*)d_in[15];
    const float* ffn_w2 = (const float*)d_in[16];
    const float* ffn_b2 = (const float*)d_in[17];
    const float* pw_w   = (const float*)d_in[18];
    const float* pw_b   = (const float*)d_in[19];
    float* out = (float*)d_out;

    float *px, *ph, *pq, *pk, *pv, *pf;
    cudaGetSymbolAddress((void**)&px, g_x);
    cudaGetSymbolAddress((void**)&ph, g_h);
    cudaGetSymbolAddress((void**)&pq, g_q);
    cudaGetSymbolAddress((void**)&pk, g_k);
    cudaGetSymbolAddress((void**)&pv, g_v);
    cudaGetSymbolAddress((void**)&pf, g_f1);

    // row attention needs 2*256*48 + 48*48 + 48 floats = 107712 B of dynamic smem
    cudaFuncSetAttribute(attn_kernel, cudaFuncAttributeMaxDynamicSharedMemorySize, 110592);

    dim3 lnBlk(32, 8);
    dim3 g192(TT / BM, CC / BN);   // (256, 3)
    dim3 g768(TT / BM, C4 / BN);   // (256, 12)

    embed_kernel<<<TT, CC>>>(tokens, emb, proj_w, proj_b, px);

    for (int i = 0; i < NBLK; i++) {
        for (int dir = 0; dir < 2; dir++) {
            const float* lg = ln_g + (size_t)(i * 3 + dir) * CC;
            const float* lb = ln_b + (size_t)(i * 3 + dir) * CC;
            ln_kernel<<<TT / 8, lnBlk>>>(px, ph, lg, lb);

            size_t woff = ((size_t)i * 2 + dir) * CC * CC;
            size_t boff = ((size_t)i * 2 + dir) * CC;
            gemm_kernel<<<g192, 256>>>(ph, wq + woff, bq + boff, pq, CC, CC, 1, 0);
            gemm_kernel<<<g192, 256>>>(ph, wk + woff, bk + boff, pk, CC, CC, 2, 0);
            gemm_kernel<<<g192, 256>>>(ph, wv + woff, bv + boff, pv, CC, CC, 0, 0);

            int N      = (dir == 0) ? LL : SS;
            int groups = (dir == 0) ? BB * SS : BB * LL;
            size_t smem = (size_t)(2 * N * DH + DH * DH + DH) * sizeof(float);
            attn_kernel<<<dim3(groups, HH), 256, smem>>>(pq, pk, pv, ph, N, dir);

            gemm_kernel<<<g192, 256>>>(ph, wo + woff, bo + boff, px, CC, CC, 0, 1);
        }
        // FFN
        const float* lg = ln_g + (size_t)(i * 3 + 2) * CC;
        const float* lb = ln_b + (size_t)(i * 3 + 2) * CC;
        ln_kernel<<<TT / 8, lnBlk>>>(px, ph, lg, lb);
        gemm_kernel<<<g768, 256>>>(ph, ffn_w1 + (size_t)i * C4 * CC, ffn_b1 + (size_t)i * C4,
                                   pf, CC, C4, 3, 0);
        gemm_kernel<<<g192, 256>>>(pf, ffn_w2 + (size_t)i * CC * C4, ffn_b2 + (size_t)i * CC,
                                   px, C4, CC, 0, 1);
    }

    final_kernel<<<TT / 8, lnBlk>>>(px, pw_w, pw_b, out);
}

// round 2
// speedup vs baseline: 1.3446x; 1.3446x over previous
#include <cuda_runtime.h>
#include <math.h>

// ---------------- problem constants ----------------
#define BB 2
#define SS 64
#define LL 256
#define CC 192
#define C4 768
#define HH 4
#define DH 48
#define TT (BB*SS*LL)      // 32768 tokens
#define NBLK 6

// ---------------- scratch (device globals; no runtime alloc) ----------------
__device__ float g_x[TT*CC];   // residual stream, layout (b,s,l,c) token-major
__device__ float g_h[TT*CC];   // LN output / attention output (reused)
__device__ float g_q[TT*CC];
__device__ float g_k[TT*CC];
__device__ float g_v[TT*CC];
__device__ float g_f1[TT*C4];  // FFN hidden

// ---------------- activation helpers ----------------
__device__ __forceinline__ float elu1(float v) {           // elu(v)+1
    return v > 0.0f ? v + 1.0f : expf(v);
}
__device__ __forceinline__ float gelu_exact(float v) {
    return 0.5f * v * (1.0f + erff(v * 0.70710678118654752f));
}
__device__ __forceinline__ unsigned int f2tf32(float f) {
    unsigned int u;
    asm("cvt.rna.tf32.f32 %0, %1;" : "=r"(u) : "f"(f));
    return u;
}

// ============================================================
// Kernel 1: embedding lookup + projection (64->192) + rotary over L
// ============================================================
__global__ void embed_kernel(const int* __restrict__ tokens,
                             const float* __restrict__ emb,
                             const float* __restrict__ pw,   // (192,64)
                             const float* __restrict__ pb,   // (192,)
                             float* __restrict__ out) {
    int t = blockIdx.x;
    int c = threadIdx.x;
    __shared__ float e[64];
    __shared__ float xv[CC];
    __shared__ float invf[96];
    if (c < 64) e[c] = emb[tokens[t] * 64 + c];
    if (c >= 64 && c < 160) {
        int j = c - 64;
        invf[j] = powf(10000.0f, -(float)j / 96.0f);
    }
    __syncthreads();
    float s = pb[c];
    const float* wr = pw + c * 64;
    #pragma unroll
    for (int i = 0; i < 64; i++) s += e[i] * wr[i];
    xv[c] = s;
    __syncthreads();
    int l = t & (LL - 1);                 // position along L
    int c2 = (c < 96) ? c : c - 96;
    float a = (float)l * invf[c2];
    float cs = cosf(a), sn = sinf(a);
    float rot = (c < 96) ? -xv[c + 96] : xv[c - 96];
    out[(size_t)t * CC + c] = s * cs + rot * sn;
}

// ============================================================
// Kernel 2: LayerNorm over the 192 channels of each token
// ============================================================
__global__ void ln_kernel(const float* __restrict__ x, float* __restrict__ h,
                          const float* __restrict__ g, const float* __restrict__ b) {
    int t = blockIdx.x * 8 + threadIdx.y;
    int lane = threadIdx.x;
    const float* xr = x + (size_t)t * CC;
    float v[6];
    float s = 0.f, ss = 0.f;
    #pragma unroll
    for (int i = 0; i < 6; i++) {
        v[i] = xr[lane + i * 32];
        s += v[i]; ss += v[i] * v[i];
    }
    #pragma unroll
    for (int o = 16; o; o >>= 1) {
        s  += __shfl_xor_sync(0xffffffffu, s, o);
        ss += __shfl_xor_sync(0xffffffffu, ss, o);
    }
    float m   = s * (1.0f / CC);
    float var = ss * (1.0f / CC) - m * m;
    float r   = rsqrtf(var + 1e-5f);
    float* hr = h + (size_t)t * CC;
    #pragma unroll
    for (int i = 0; i < 6; i++) {
        int c = lane + i * 32;
        hr[c] = (v[i] - m) * r * g[c] + b[c];
    }
}

// ============================================================
// Kernel 3: TF32 tensor-core GEMM
//   C[t,o] = act( A[t,:K] . W[o,:K] + bias[o] ) (+ C)
// A: (T,K) row-major fp32, W: (N,K) row-major fp32.
// Block tile 128x64, 8 warps (4x2), warp tile 32x32 (2x4 mma m16n8k8 tf32).
// act: 0 none, 1 (elu+1)/sqrt(48), 2 elu+1, 3 gelu ; accFlag: += existing
// ============================================================
#define BM 128
#define BN 64
#define BK 16
#define PADK 20     // floats per shared row (pad 4): conflict-free + 16B aligned

__global__ __launch_bounds__(256) void gemm_kernel(
        const float* __restrict__ A, const float* __restrict__ W,
        const float* __restrict__ bias, float* __restrict__ Cout,
        int K, int N, int act, int accFlag) {
    __shared__ unsigned int As[BM * PADK];
    __shared__ unsigned int Bs[BN * PADK];
    int tid  = threadIdx.x;
    int lane = tid & 31;
    int warp = tid >> 5;
    int warpM = warp >> 1;        // 0..3
    int warpN = warp & 1;         // 0..1
    int gid = lane >> 2;          // 0..7
    int tig = lane & 3;           // 0..3
    int row0 = blockIdx.x * BM;
    int col0 = blockIdx.y * BN;

    float acc[2][4][4];
    #pragma unroll
    for (int i = 0; i < 2; i++)
        #pragma unroll
        for (int j = 0; j < 4; j++)
            #pragma unroll
            for (int q = 0; q < 4; q++) acc[i][j][q] = 0.f;

    for (int k0 = 0; k0 < K; k0 += BK) {
        // stage A tile (128x16) as tf32
        #pragma unroll
        for (int i = 0; i < 2; i++) {
            int lin = tid + i * 256;
            int m  = lin >> 2;
            int kq = (lin & 3) << 2;
            float4 f = *(const float4*)&A[(size_t)(row0 + m) * K + k0 + kq];
            unsigned int* dst = &As[m * PADK + kq];
            dst[0] = f2tf32(f.x); dst[1] = f2tf32(f.y);
            dst[2] = f2tf32(f.z); dst[3] = f2tf32(f.w);
        }
        // stage B tile (64x16) as tf32
        {
            int m  = tid >> 2;
            int kq = (tid & 3) << 2;
            float4 f = *(const float4*)&W[(size_t)(col0 + m) * K + k0 + kq];
            unsigned int* dst = &Bs[m * PADK + kq];
            dst[0] = f2tf32(f.x); dst[1] = f2tf32(f.y);
            dst[2] = f2tf32(f.z); dst[3] = f2tf32(f.w);
        }
        __syncthreads();

        #pragma unroll
        for (int ks = 0; ks < 2; ks++) {
            int kk = ks * 8;
            unsigned int af[2][4], bf[4][2];
            #pragma unroll
            for (int mt = 0; mt < 2; mt++) {
                int r = warpM * 32 + mt * 16 + gid;
                af[mt][0] = As[r * PADK + kk + tig];
                af[mt][1] = As[(r + 8) * PADK + kk + tig];
                af[mt][2] = As[r * PADK + kk + tig + 4];
                af[mt][3] = As[(r + 8) * PADK + kk + tig + 4];
            }
            #pragma unroll
            for (int nt = 0; nt < 4; nt++) {
                int cn = warpN * 32 + nt * 8 + gid;
                bf[nt][0] = Bs[cn * PADK + kk + tig];
                bf[nt][1] = Bs[cn * PADK + kk + tig + 4];
            }
            #pragma unroll
            for (int mt = 0; mt < 2; mt++)
                #pragma unroll
                for (int nt = 0; nt < 4; nt++) {
                    asm volatile(
                        "mma.sync.aligned.m16n8k8.row.col.f32.tf32.tf32.f32 "
                        "{%0,%1,%2,%3}, {%4,%5,%6,%7}, {%8,%9}, {%0,%1,%2,%3};"
                        : "+f"(acc[mt][nt][0]), "+f"(acc[mt][nt][1]),
                          "+f"(acc[mt][nt][2]), "+f"(acc[mt][nt][3])
                        : "r"(af[mt][0]), "r"(af[mt][1]), "r"(af[mt][2]), "r"(af[mt][3]),
                          "r"(bf[nt][0]), "r"(bf[nt][1]));
                }
        }
        __syncthreads();
    }

    // epilogue: c0,c1 -> (row, col+{0,1}); c2,c3 -> (row+8, col+{0,1})
    #pragma unroll
    for (int mt = 0; mt < 2; mt++) {
        int r0 = row0 + warpM * 32 + mt * 16 + gid;
        #pragma unroll
        for (int nt = 0; nt < 4; nt++) {
            int c0 = col0 + warpN * 32 + nt * 8 + tig * 2;
            #pragma unroll
            for (int half = 0; half < 2; half++) {
                int r = r0 + half * 8;
                #pragma unroll
                for (int q = 0; q < 2; q++) {
                    int c = c0 + q;
                    float v = acc[mt][nt][half * 2 + q] + bias[c];
                    if (act == 1)      v = elu1(v) * 0.14433756729740643f;  // 1/sqrt(48)
                    else if (act == 2) v = elu1(v);
                    else if (act == 3) v = gelu_exact(v);
                    size_t idx = (size_t)r * N + c;
                    if (accFlag) v += Cout[idx];
                    Cout[idx] = v;
                }
            }
        }
    }
}

// ============================================================
// Kernel 4: linear attention core per (group, head)
// ============================================================
__global__ __launch_bounds__(256) void attn_kernel(
        const float* __restrict__ q, const float* __restrict__ k,
        const float* __restrict__ v, float* __restrict__ o,
        int N, int isCol) {
    extern __shared__ float sm[];
    float* ks   = sm;                 // N*48
    float* vs   = sm + N * DH;        // N*48
    float* kv   = vs + N * DH;        // 48*48
    float* ksum = kv + DH * DH;       // 48
    int g = blockIdx.x, h = blockIdx.y;
    int tid = threadIdx.x;

    for (int lin = tid; lin < N * (DH / 4); lin += 256) {
        int n = lin / (DH / 4);
        int j = lin - n * (DH / 4);
        int t = isCol ? ((((g >> 8) * SS + n) << 8) + (g & 255)) : g * N + n;
        size_t base = (size_t)t * CC + h * DH;
        ((float4*)ks)[n * (DH / 4) + j] = *(const float4*)(k + base + j * 4);
        ((float4*)vs)[n * (DH / 4) + j] = *(const float4*)(v + base + j * 4);
    }
    __syncthreads();

    if (tid < DH) {
        float s = 0.f;
        for (int n = 0; n < N; n++) s += ks[n * DH + tid];
        ksum[tid] = s;
    }
    for (int p = tid; p < DH * DH; p += 256) {
        int d = p / DH, e = p - d * DH;
        float s = 0.f;
        for (int n = 0; n < N; n++) s += ks[n * DH + d] * vs[n * DH + e];
        kv[p] = s;
    }
    __syncthreads();

    for (int n = tid; n < N; n += 256) {
        int t = isCol ? ((((g >> 8) * SS + n) << 8) + (g & 255)) : g * N + n;
        size_t base = (size_t)t * CC + h * DH;
        float qr[DH];
        #pragma unroll
        for (int j = 0; j < DH / 4; j++) {
            float4 f = *(const float4*)(q + base + j * 4);
            qr[4*j] = f.x; qr[4*j+1] = f.y; qr[4*j+2] = f.z; qr[4*j+3] = f.w;
        }
        float qk = 0.f;
        #pragma unroll
        for (int d = 0; d < DH; d++) qk += qr[d] * ksum[d];
        float z = 1.0f / (qk + 1e-6f);
        float ov[DH];
        #pragma unroll
        for (int e = 0; e < DH; e++) ov[e] = 0.f;
        #pragma unroll
        for (int d = 0; d < DH; d++) {
            float qd = qr[d];
            const float4* kvr = (const float4*)&kv[d * DH];
            #pragma unroll
            for (int j = 0; j < DH / 4; j++) {
                float4 kk4 = kvr[j];
                ov[4*j]   += qd * kk4.x;
                ov[4*j+1] += qd * kk4.y;
                ov[4*j+2] += qd * kk4.z;
                ov[4*j+3] += qd * kk4.w;
            }
        }
        #pragma unroll
        for (int j = 0; j < DH / 4; j++) {
            float4 w4 = make_float4(ov[4*j]*z, ov[4*j+1]*z, ov[4*j+2]*z, ov[4*j+3]*z);
            *(float4*)(o + base + j * 4) = w4;
        }
    }
}

// ============================================================
// Kernel 5: head — o = sigmoid(softplus(x . pw + pb))
// ============================================================
__global__ void final_kernel(const float* __restrict__ x,
                             const float* __restrict__ pw,
                             const float* __restrict__ pb,
                             float* __restrict__ out) {
    int t = blockIdx.x * 8 + threadIdx.y;
    int lane = threadIdx.x;
    const float* xr = x + (size_t)t * CC;
    float s = 0.f;
    #pragma unroll
    for (int i = 0; i < 6; i++) {
        int c = lane + i * 32;
        s += xr[c] * pw[c];
    }
    #pragma unroll
    for (int o = 16; o; o >>= 1) s += __shfl_xor_sync(0xffffffffu, s, o);
    if (lane == 0) {
        float ov = s + pb[0];
        float sp = (ov > 20.f) ? ov : log1pf(expf(ov));
        out[t] = 1.0f / (1.0f + expf(-sp));
    }
}

// ============================================================
// Host orchestration
// ============================================================
extern "C" void kernel_launch(void* const* d_in, const int* in_sizes, int n_in,
                              void* d_out, int out_size) {
    const int*   tokens = (const int*)  d_in[0];
    const float* emb    = (const float*)d_in[1];
    const float* proj_w = (const float*)d_in[2];
    const float* proj_b = (const float*)d_in[3];
    const float* ln_g   = (const float*)d_in[4];
    const float* ln_b   = (const float*)d_in[5];
    const float* wq     = (const float*)d_in[6];
    const float* wk     = (const float*)d_in[7];
    const float* wv     = (const float*)d_in[8];
    const float* wo     = (const float*)d_in[9];
    const float* bq     = (const float*)d_in[10];
    const float* bk     = (const float*)d_in[11];
    const float* bv     = (const float*)d_in[12];
    const float* bo     = (const float*)d_in[13];
    const float* ffn_w1 = (const float*)d_in[14];
    const float* ffn_b1 = (const float*)d_in[15];
    const float* ffn_w2 = (const float*)d_in[16];
    const float* ffn_b2 = (const float*)d_in[17];
    const float* pw_w   = (const float*)d_in[18];
    const float* pw_b   = (const float*)d_in[19];
    float* out = (float*)d_out;

    float *px, *ph, *pq, *pk, *pv, *pf;
    cudaGetSymbolAddress((void**)&px, g_x);
    cudaGetSymbolAddress((void**)&ph, g_h);
    cudaGetSymbolAddress((void**)&pq, g_q);
    cudaGetSymbolAddress((void**)&pk, g_k);
    cudaGetSymbolAddress((void**)&pv, g_v);
    cudaGetSymbolAddress((void**)&pf, g_f1);

    cudaFuncSetAttribute(attn_kernel, cudaFuncAttributeMaxDynamicSharedMemorySize, 110592);

    dim3 lnBlk(32, 8);
    dim3 g192(TT / BM, CC / BN);   // (256, 3)
    dim3 g768(TT / BM, C4 / BN);   // (256, 12)

    embed_kernel<<<TT, CC>>>(tokens, emb, proj_w, proj_b, px);

    for (int i = 0; i < NBLK; i++) {
        for (int dir = 0; dir < 2; dir++) {
            const float* lg = ln_g + (size_t)(i * 3 + dir) * CC;
            const float* lb = ln_b + (size_t)(i * 3 + dir) * CC;
            ln_kernel<<<TT / 8, lnBlk>>>(px, ph, lg, lb);

            size_t woff = ((size_t)i * 2 + dir) * CC * CC;
            size_t boff = ((size_t)i * 2 + dir) * CC;
            gemm_kernel<<<g192, 256>>>(ph, wq + woff, bq + boff, pq, CC, CC, 1, 0);
            gemm_kernel<<<g192, 256>>>(ph, wk + woff, bk + boff, pk, CC, CC, 2, 0);
            gemm_kernel<<<g192, 256>>>(ph, wv + woff, bv + boff, pv, CC, CC, 0, 0);

            int N      = (dir == 0) ? LL : SS;
            int groups = (dir == 0) ? BB * SS : BB * LL;
            size_t smem = (size_t)(2 * N * DH + DH * DH + DH) * sizeof(float);
            attn_kernel<<<dim3(groups, HH), 256, smem>>>(pq, pk, pv, ph, N, dir);

            gemm_kernel<<<g192, 256>>>(ph, wo + woff, bo + boff, px, CC, CC, 0, 1);
        }
        // FFN
        const float* lg = ln_g + (size_t)(i * 3 + 2) * CC;
        const float* lb = ln_b + (size_t)(i * 3 + 2) * CC;
        ln_kernel<<<TT / 8, lnBlk>>>(px, ph, lg, lb);
        gemm_kernel<<<g768, 256>>>(ph, ffn_w1 + (size_t)i * C4 * CC, ffn_b1 + (size_t)i * C4,
                                   pf, CC, C4, 3, 0);
        gemm_kernel<<<g192, 256>>>(pf, ffn_w2 + (size_t)i * CC * C4, ffn_b2 + (size_t)i * CC,
                                   px, C4, CC, 0, 1);
    }

    final_kernel<<<TT / 8, lnBlk>>>(px, pw_w, pw_b, out);
}